// round 5
// baseline (speedup 1.0000x reference)
#include <cuda_runtime.h>
#include <cstdint>

#define IMG_N  2048
#define OW     2044
#define OH     2044
#define TW     128
#define TH     8
#define IR     12          // TH + 4 input rows
#define IC     132         // TW + 4 input cols
#define NTH    256

#define PSTR   132         // fp32 plane col stride (floats), 528B rows (16B aligned)

// smem layout (bytes)
#define SX_OFF     0                               // int tile [IR][IC]
#define SX_BYTES   (IR * IC * 4)                   // 6336
#define PL_OFF     SX_BYTES                        // fp32 planes [IR][9][PSTR]
#define PL_BYTES   (IR * 9 * PSTR * 4)             // 57024
#define W_OFF      (PL_OFF + PL_BYTES)             // 63360
#define SMEM_BYTES (W_OFF + 75 * 8)

typedef unsigned long long ull;
typedef unsigned int u32;

__device__ __forceinline__ void fma2(ull& acc, ull a, ull b) {
    asm("fma.rn.f32x2 %0, %1, %2, %0;" : "+l"(acc) : "l"(a), "l"(b));
}
__device__ __forceinline__ ull pack2(u32 lo, u32 hi) {
    ull r; asm("mov.b64 %0, {%1, %2};" : "=l"(r) : "r"(lo), "r"(hi)); return r;
}

// Expand 9 bit-planes [ZLO..ZLO+8] of the int tile into fp32 planes.
__device__ __forceinline__ void expand_planes(const int* __restrict__ sx,
                                              float* __restrict__ pl,
                                              int tid, int ZLO)
{
    for (int idx = tid; idx < IR * IC; idx += NTH) {
        int rr = idx / IC, cc = idx - rr * IC;
        u32 v = (u32)sx[idx];
        float* dst = pl + (rr * 9) * PSTR + cc;
        #pragma unroll
        for (int kk = 0; kk < 9; kk++) {
            u32 f = ((v >> (ZLO + kk)) & 1u) * 0x3F800000u;
            *reinterpret_cast<u32*>(dst + kk * PSTR) = f;
        }
    }
}

// One z-pass: outputs z in [ZLO, ZLO+6] from planes kk in [0..8] (k = ZLO+kk).
__device__ __forceinline__ void run_pass(const float* __restrict__ pl,
                                         const ull* __restrict__ wps,
                                         int r, int col0, ull* accA, ull* accB)
{
    #pragma unroll
    for (int z = 0; z < 7; z++) { accA[z] = 0ull; accB[z] = 0ull; }

    #pragma unroll 1
    for (int i = 0; i < 5; i++) {
        ull wv[15];
        #pragma unroll
        for (int d = 0; d < 3; d++)
            #pragma unroll
            for (int j = 0; j < 5; j++)
                wv[d * 5 + j] = wps[d * 25 + i * 5 + j];

        const float* rowi = pl + ((r + i) * 9) * PSTR + col0;

        #pragma unroll
        for (int kk = 0; kk < 9; kk++) {
            const u32* rk = reinterpret_cast<const u32*>(rowi + kk * PSTR);
            uint4 a = *reinterpret_cast<const uint4*>(rk);       // v0..v3 (aligned quad)
            uint4 b = *reinterpret_cast<const uint4*>(rk + 4);   // v4..v7

            ull S[7];
            S[0] = pack2(a.x, a.y);   // aligned in-place (no movs)
            S[2] = pack2(a.z, a.w);
            S[4] = pack2(b.x, b.y);
            S[6] = pack2(b.z, b.w);
            S[1] = pack2(a.y, a.z);   // cross: 2 movs
            S[3] = pack2(a.w, b.x);
            S[5] = pack2(b.y, b.z);

            #pragma unroll
            for (int d = 0; d < 3; d++) {
                const int zz = kk - d;
                if (zz >= 0 && zz < 7) {
                    #pragma unroll
                    for (int j = 0; j < 5; j++) {
                        fma2(accA[zz], wv[d * 5 + j], S[j]);       // cols (c, c+1)
                        fma2(accB[zz], wv[d * 5 + j], S[j + 2]);   // cols (c+2, c+3)
                    }
                }
            }
        }
    }
}

__device__ __forceinline__ void store_pass(float* __restrict__ out, int h, int w,
                                           int ZLO, float bv,
                                           const ull* accA, const ull* accB)
{
    if (h >= OH || w >= OW) return;
    const bool full = (w + 4 <= OW);
    #pragma unroll
    for (int zz = 0; zz < 7; zz++) {
        float2 a = *reinterpret_cast<const float2*>(&accA[zz]);
        float2 b = *reinterpret_cast<const float2*>(&accB[zz]);
        size_t off = ((size_t)(ZLO + zz) * OH + h) * OW + w;
        if (full) {
            float4 v = make_float4(a.x + bv, a.y + bv, b.x + bv, b.y + bv);
            *reinterpret_cast<float4*>(out + off) = v;
        } else {
            float vals[4] = { a.x + bv, a.y + bv, b.x + bv, b.y + bv };
            #pragma unroll
            for (int c = 0; c < 4; c++)
                if (w + c < OW) out[off + c] = vals[c];
        }
    }
}

__global__ void __launch_bounds__(NTH, 3)
conv2dto3d_kernel(const int* __restrict__ x,
                  const float* __restrict__ weight,
                  const float* __restrict__ bias,
                  float* __restrict__ out)
{
    extern __shared__ unsigned char smem[];
    int*   sx  = reinterpret_cast<int*>(smem + SX_OFF);
    float* pl  = reinterpret_cast<float*>(smem + PL_OFF);
    ull*   wps = reinterpret_cast<ull*>(smem + W_OFF);

    const int tid   = threadIdx.x;
    const int wbase = blockIdx.x * TW;
    const int hbase = blockIdx.y * TH;

    if (tid < 75) {
        u32 wb = __float_as_uint(weight[tid]);
        wps[tid] = pack2(wb, wb);
    }

    // ---- load int tile (clamped) ----
    for (int idx = tid; idx < IR * IC; idx += NTH) {
        int rr = idx / IC, cc = idx - rr * IC;
        int ri = hbase + rr; if (ri > IMG_N - 1) ri = IMG_N - 1;
        int ci = wbase + cc; if (ci > IMG_N - 1) ci = IMG_N - 1;
        sx[idx] = x[ri * IMG_N + ci];
    }
    __syncthreads();

    const int g = tid & 31;
    const int r = tid >> 5;
    const int col0 = g * 4;
    const int h = hbase + r;
    const int w = wbase + col0;
    const float bv = bias[0];

    ull accA[7], accB[7];

    // ---- pass 0: z in [0..6], bit planes 0..8 ----
    expand_planes(sx, pl, tid, 0);
    __syncthreads();
    run_pass(pl, wps, r, col0, accA, accB);
    store_pass(out, h, w, 0, bv, accA, accB);
    __syncthreads();

    // ---- pass 1: z in [7..13], bit planes 7..15 ----
    expand_planes(sx, pl, tid, 7);
    __syncthreads();
    run_pass(pl, wps, r, col0, accA, accB);
    store_pass(out, h, w, 7, bv, accA, accB);
}

extern "C" void kernel_launch(void* const* d_in, const int* in_sizes, int n_in,
                              void* d_out, int out_size)
{
    const int*   x      = (const int*)d_in[0];
    const float* weight = (const float*)d_in[1];
    const float* bias   = (const float*)d_in[2];
    float*       out    = (float*)d_out;

    cudaFuncSetAttribute(conv2dto3d_kernel,
                         cudaFuncAttributeMaxDynamicSharedMemorySize, SMEM_BYTES);

    dim3 grid((OW + TW - 1) / TW, (OH + TH - 1) / TH);   // 16 x 256
    conv2dto3d_kernel<<<grid, NTH, SMEM_BYTES>>>(x, weight, bias, out);
}

// round 6
// speedup vs baseline: 1.3271x; 1.3271x over previous
#include <cuda_runtime.h>
#include <cstdint>

#define IMG_N  2048
#define OW     2044
#define OH     2044
#define TW     128
#define TH     8
#define IR     12          // TH + 4 input rows
#define IC     132         // TW + 4 input cols
#define ICP    136         // padded col stride (bf16 elements)
#define NTH    256

#define PLANES_U16 (IR * 16 * ICP)           // 26112 bf16
#define WOFF       (PLANES_U16 * 2)          // 52224 bytes
// weights padded: 15 rows (d*5+i) x 8 ull slots (j in 0..4) -> rows 64B aligned
#define SMEM_BYTES (WOFF + 15 * 8 * 8)

typedef unsigned long long ull;
typedef unsigned int u32;

__device__ __forceinline__ void fma2(ull& acc, ull a, ull b) {
    asm("fma.rn.f32x2 %0, %1, %2, %0;" : "+l"(acc) : "l"(a), "l"(b));
}
__device__ __forceinline__ ull pack2(u32 lo, u32 hi) {
    ull r; asm("mov.b64 %0, {%1, %2};" : "=l"(r) : "r"(lo), "r"(hi)); return r;
}
__device__ __forceinline__ ull mkpair_lohi(u32 u) {
    ull r;
    asm("{.reg .b32 a, b;\n\t"
        "shl.b32 a, %1, 16;\n\t"
        "and.b32 b, %1, 0xFFFF0000;\n\t"
        "mov.b64 %0, {a, b};}" : "=l"(r) : "r"(u));
    return r;
}
__device__ __forceinline__ ull mkpair_cross(u32 u, u32 v) {
    ull r;
    asm("{.reg .b32 a, b;\n\t"
        "and.b32 a, %1, 0xFFFF0000;\n\t"
        "shl.b32 b, %2, 16;\n\t"
        "mov.b64 %0, {a, b};}" : "=l"(r) : "r"(u), "r"(v));
    return r;
}

// One z-pass: outputs z in [ZLO, ZLO+6], consuming bit planes k in [ZLO, ZLO+8].
template<int ZLO>
__device__ __forceinline__ void run_pass(const uint16_t* __restrict__ sp,
                                         const ull* __restrict__ wps,
                                         int r, int col0, ull* accA, ull* accB)
{
    #pragma unroll
    for (int z = 0; z < 7; z++) { accA[z] = 0ull; accB[z] = 0ull; }

    #pragma unroll 1
    for (int i = 0; i < 5; i++) {
        const uint16_t* rowi = sp + ((r + i) * 16 + ZLO) * ICP + col0;
        const ull* wrow = wps + i * 8;              // row (d*5+i)*8, d added below

        #pragma unroll
        for (int kk = 0; kk < 9; kk++) {
            const u32* rk = reinterpret_cast<const u32*>(rowi + kk * ICP);
            uint2 ma = *reinterpret_cast<const uint2*>(rk);       // bf16 cols 0..3
            uint2 mb = *reinterpret_cast<const uint2*>(rk + 2);   // bf16 cols 4..7

            ull S[7];
            S[0] = mkpair_lohi (ma.x);
            S[1] = mkpair_cross(ma.x, ma.y);
            S[2] = mkpair_lohi (ma.y);
            S[3] = mkpair_cross(ma.y, mb.x);
            S[4] = mkpair_lohi (mb.x);
            S[5] = mkpair_cross(mb.x, mb.y);
            S[6] = mkpair_lohi (mb.y);

            #pragma unroll
            for (int d = 0; d < 3; d++) {
                const int zz = kk - d;              // compile-time per (kk,d)
                if (zz >= 0 && zz < 7) {
                    // load this d-group's 5 weight pairs (broadcast LDS)
                    const ull* wd = wrow + d * 40;  // (d*5+i)*8
                    ulonglong2 w01 = *reinterpret_cast<const ulonglong2*>(wd);
                    ulonglong2 w23 = *reinterpret_cast<const ulonglong2*>(wd + 2);
                    ull        w4  = wd[4];
                    fma2(accA[zz], w01.x, S[0]);  fma2(accB[zz], w01.x, S[2]);
                    fma2(accA[zz], w01.y, S[1]);  fma2(accB[zz], w01.y, S[3]);
                    fma2(accA[zz], w23.x, S[2]);  fma2(accB[zz], w23.x, S[4]);
                    fma2(accA[zz], w23.y, S[3]);  fma2(accB[zz], w23.y, S[5]);
                    fma2(accA[zz], w4,    S[4]);  fma2(accB[zz], w4,    S[6]);
                }
            }
        }
    }
}

template<int ZLO>
__device__ __forceinline__ void store_pass(float* __restrict__ out, int h, int w,
                                           float bv, const ull* accA, const ull* accB)
{
    if (h >= OH || w >= OW) return;
    const bool full = (w + 4 <= OW);
    #pragma unroll
    for (int zz = 0; zz < 7; zz++) {
        float2 a = *reinterpret_cast<const float2*>(&accA[zz]);
        float2 b = *reinterpret_cast<const float2*>(&accB[zz]);
        size_t off = ((size_t)(ZLO + zz) * OH + h) * OW + w;
        if (full) {
            float4 v = make_float4(a.x + bv, a.y + bv, b.x + bv, b.y + bv);
            *reinterpret_cast<float4*>(out + off) = v;
        } else {
            float vals[4] = { a.x + bv, a.y + bv, b.x + bv, b.y + bv };
            #pragma unroll
            for (int c = 0; c < 4; c++)
                if (w + c < OW) out[off + c] = vals[c];
        }
    }
}

__global__ void __launch_bounds__(NTH, 4)
conv2dto3d_kernel(const int* __restrict__ x,
                  const float* __restrict__ weight,
                  const float* __restrict__ bias,
                  float* __restrict__ out)
{
    extern __shared__ unsigned char smem[];
    uint16_t* sp  = reinterpret_cast<uint16_t*>(smem);
    ull*      wps = reinterpret_cast<ull*>(smem + WOFF);

    const int tid   = threadIdx.x;
    const int wbase = blockIdx.x * TW;
    const int hbase = blockIdx.y * TH;

    // weight pairs into padded layout: slot (d*5+i)*8 + j
    if (tid < 75) {
        int d = tid / 25, rem = tid - d * 25;
        int i = rem / 5,  j = rem - i * 5;
        u32 wb = __float_as_uint(weight[tid]);
        wps[(d * 5 + i) * 8 + j] = pack2(wb, wb);
    }

    // ---- expand tile to bf16 bit planes: sp[rr][k][cc] = bit k of pixel (exact) ----
    for (int pp = tid; pp < IR * (IC / 2); pp += NTH) {
        int rr = pp / (IC / 2);
        int c2 = (pp - rr * (IC / 2)) * 2;
        int ri = hbase + rr;     if (ri > IMG_N - 1) ri = IMG_N - 1;
        int c0 = wbase + c2;     if (c0 > IMG_N - 1) c0 = IMG_N - 1;
        int c1 = wbase + c2 + 1; if (c1 > IMG_N - 1) c1 = IMG_N - 1;
        u32 a0 = (u32)x[ri * IMG_N + c0];
        u32 a1 = (u32)x[ri * IMG_N + c1];
        #pragma unroll
        for (int k = 0; k < 16; k++) {
            u32 val = ((a0 >> k) & 1u) * 0x3F80u
                    | ((a1 >> k) & 1u) * 0x3F800000u;
            *reinterpret_cast<u32*>(sp + (rr * 16 + k) * ICP + c2) = val;
        }
    }
    __syncthreads();

    const int g = tid & 31;
    const int r = tid >> 5;
    const int col0 = g * 4;
    const int h = hbase + r;
    const int w = wbase + col0;
    const float bv = bias[0];

    ull accA[7], accB[7];

    run_pass<0>(sp, wps, r, col0, accA, accB);
    store_pass<0>(out, h, w, bv, accA, accB);

    run_pass<7>(sp, wps, r, col0, accA, accB);
    store_pass<7>(out, h, w, bv, accA, accB);
}

extern "C" void kernel_launch(void* const* d_in, const int* in_sizes, int n_in,
                              void* d_out, int out_size)
{
    const int*   x      = (const int*)d_in[0];
    const float* weight = (const float*)d_in[1];
    const float* bias   = (const float*)d_in[2];
    float*       out    = (float*)d_out;

    cudaFuncSetAttribute(conv2dto3d_kernel,
                         cudaFuncAttributeMaxDynamicSharedMemorySize, SMEM_BYTES);

    dim3 grid((OW + TW - 1) / TW, (OH + TH - 1) / TH);   // 16 x 256
    conv2dto3d_kernel<<<grid, NTH, SMEM_BYTES>>>(x, weight, bias, out);
}